// round 1
// baseline (speedup 1.0000x reference)
#include <cuda_runtime.h>
#include <math.h>

#define SEQ   4096
#define LW    24
#define EMBD  300
#define CHOUT 25
#define CHE   25
#define HIDN  512
#define INPD  325      // EMB + CH_OUT
#define EMBS  328      // padded stride for 16B alignment
#define NTAG  11
#define STARTT 9
#define STOPT  10
#define NEGV  -10000.0f
#define NGATE 2048     // 4*HIDN

// ---------------- static device scratch (no allocs allowed) ----------------
__device__ float g_emb[SEQ * EMBS];           // 5.4 MB  [t][k]
__device__ float g_G[2][SEQ * NGATE];         // 64 MB   Wih@x + bih + bhh
__device__ float g_h[2][SEQ * HIDN];          // 16 MB   hidden states
__device__ float g_feats[SEQ * 16];           // padded [t][tag]
__device__ int   g_ready[2 * SEQ];            // per-step producer counters

// ---------------- helpers ----------------
__device__ __forceinline__ int ld_acq(const int* p) {
    int v;
    asm volatile("ld.global.acquire.gpu.b32 %0, [%1];" : "=r"(v) : "l"(p));
    return v;
}
__device__ __forceinline__ float sigf(float x) { return 1.0f / (1.0f + __expf(-x)); }

// ---------------- reset per-step counters (graph replays reuse state) -------
__global__ void zero_ready_kernel() {
    int i = blockIdx.x * blockDim.x + threadIdx.x;
    if (i < 2 * SEQ) g_ready[i] = 0;
}

// ---------------- char CNN + word-embedding gather --------------------------
__global__ void embed_kernel(const int* __restrict__ sentence,
                             const int* __restrict__ chars,
                             const float* __restrict__ word_emb,
                             const float* __restrict__ char_emb,
                             const float* __restrict__ conv_w,
                             const float* __restrict__ conv_b) {
    int s = blockIdx.x;
    int tid = threadIdx.x;
    __shared__ float ce[LW][CHE];
    __shared__ float co[CHOUT][26];
    __shared__ int   cidx[LW];

    if (tid < LW) cidx[tid] = chars[s * LW + tid];
    __syncthreads();
    for (int idx = tid; idx < LW * CHE; idx += blockDim.x) {
        int r = idx / CHE, e = idx % CHE;
        ce[r][e] = char_emb[cidx[r] * CHE + e];
    }
    __syncthreads();
    // conv out positions p in [0,26), kernel (3, CHE), pad 2 on each side of L
    for (int idx = tid; idx < CHOUT * 26; idx += blockDim.x) {
        int o = idx / 26, p = idx % 26;
        float sum = 0.0f;
        #pragma unroll
        for (int kh = 0; kh < 3; kh++) {
            int r = p - 2 + kh;
            if (r >= 0 && r < LW) {
                const float* w = conv_w + (o * 3 + kh) * CHE;
                float ss = 0.0f;
                #pragma unroll
                for (int e = 0; e < CHE; e++) ss += ce[r][e] * w[e];
                sum += ss;
            }
        }
        co[o][p] = sum;
    }
    __syncthreads();
    if (tid < CHOUT) {
        float m = -3.4e38f;
        #pragma unroll
        for (int p = 0; p < 26; p++) m = fmaxf(m, co[tid][p]);
        g_emb[s * EMBS + EMBD + tid] = m + conv_b[tid];
    }
    // word embedding copy (300 floats = 75 float4, rows are 16B aligned)
    int wi = sentence[s];
    const float4* src = (const float4*)(word_emb + (size_t)wi * EMBD);
    float4* dst = (float4*)(g_emb + (size_t)s * EMBS);
    for (int i = tid; i < EMBD / 4; i += blockDim.x) dst[i] = src[i];
}

// ---------------- G = emb @ Wih^T + (bih + bhh) -----------------------------
// C[M=4096][N=2048] per dir; 64x64 tile, 256 threads, 4x4 microtile, KC=8.
__global__ __launch_bounds__(256) void gemm_kernel(
    const float* __restrict__ Wihf, const float* __restrict__ Wihb,
    const float* __restrict__ bihf, const float* __restrict__ bhhf,
    const float* __restrict__ bihb, const float* __restrict__ bhhb) {
    int dir = blockIdx.z;
    const float* Wih = dir ? Wihb : Wihf;
    const float* bih = dir ? bihb : bihf;
    const float* bhh = dir ? bhhb : bhhf;
    int bm = blockIdx.y * 64;   // t tile
    int bn = blockIdx.x * 64;   // gate-row tile
    int tid = threadIdx.x;
    int tx = tid & 15, ty = tid >> 4;

    __shared__ __align__(16) float As[8][68];
    __shared__ __align__(16) float Bs[8][68];

    float acc[4][4] = {};
    for (int k0 = 0; k0 < INPD; k0 += 8) {
        #pragma unroll
        for (int q = 0; q < 2; q++) {
            int idx = tid + q * 256;       // 512 elems
            int kk = idx & 7, m = idx >> 3; // consecutive tid -> consecutive k
            int k = k0 + kk;
            As[kk][m] = (k < INPD) ? g_emb[(size_t)(bm + m) * EMBS + k] : 0.0f;
            Bs[kk][m] = (k < INPD) ? Wih[(size_t)(bn + m) * INPD + k] : 0.0f;
        }
        __syncthreads();
        #pragma unroll
        for (int kk = 0; kk < 8; kk++) {
            float4 a = *(const float4*)&As[kk][ty * 4];
            float4 b = *(const float4*)&Bs[kk][tx * 4];
            float av[4] = {a.x, a.y, a.z, a.w};
            float bv[4] = {b.x, b.y, b.z, b.w};
            #pragma unroll
            for (int i = 0; i < 4; i++)
                #pragma unroll
                for (int j = 0; j < 4; j++) acc[i][j] += av[i] * bv[j];
        }
        __syncthreads();
    }
    float* Gp = g_G[dir];
    #pragma unroll
    for (int i = 0; i < 4; i++) {
        int t = bm + ty * 4 + i;
        #pragma unroll
        for (int j = 0; j < 4; j++) {
            int n = bn + tx * 4 + j;
            Gp[(size_t)t * NGATE + n] = acc[i][j] + bih[n] + bhh[n];
        }
    }
}

// ---------------- persistent BiLSTM recurrence -------------------------------
// 128 blocks (64 per direction), 256 threads. Block b of direction d owns
// h indices [b*8, b*8+8) -> 32 gate rows (i/f/g/o quads), Whh slice in regs.
__global__ __launch_bounds__(256, 1) void lstm_kernel(
    const float* __restrict__ Whhf, const float* __restrict__ Whhb) {
    int dir = blockIdx.x >> 6;
    int b = blockIdx.x & 63;
    int tid = threadIdx.x;
    int lr = tid >> 3;     // local row 0..31
    int cg = tid & 7;      // column group (64 cols each)
    int gate = lr >> 3, jj = lr & 7;
    int grow = gate * HIDN + b * 8 + jj;          // global gate row
    const float* Whh = dir ? Whhb : Whhf;

    // 64 weights per thread, held in registers for the whole sequence
    float4 wreg[16];
    const float4* wsrc = (const float4*)(Whh + (size_t)grow * HIDN + cg * 64);
    #pragma unroll
    for (int q = 0; q < 16; q++) wreg[q] = wsrc[q];

    __shared__ float4 hs4[8 * 17];   // swizzled h_prev (pad 1 float4 / group)
    __shared__ float  gsum[32];

    bool owner = (cg == 0) && (lr < 8);   // tid in {0,8,...,56}, owns h index jj
    int jglob = b * 8 + (tid >> 3);
    float cstate = 0.0f;
    const float* Gp = g_G[dir];
    float* hp = g_h[dir];
    int* rdy = g_ready + dir * SEQ;

    for (int s = 0; s < SEQ; s++) {
        int t = dir ? (SEQ - 1 - s) : s;
        // prefetch precomputed input projection (independent of h)
        float gi = 0.f, gf = 0.f, gg = 0.f, go = 0.f;
        if (owner) {
            const float* gr = Gp + (size_t)t * NGATE + jglob;
            gi = gr[0]; gf = gr[512]; gg = gr[1024]; go = gr[1536];
        }
        if (s > 0) {
            int pt = dir ? (t + 1) : (t - 1);
            while (ld_acq(&rdy[pt]) < 64) {}   // all threads spin (own acquire)
            if (tid < 128) {
                float4 v = ((const float4*)(hp + (size_t)pt * HIDN))[tid];
                hs4[(tid >> 4) * 17 + (tid & 15)] = v;
            }
        } else {
            if (tid < 136) hs4[tid] = make_float4(0.f, 0.f, 0.f, 0.f);
        }
        __syncthreads();

        // partial dot: 64 columns per thread
        float acc = 0.0f;
        const float4* hrow = hs4 + cg * 17;
        #pragma unroll
        for (int q = 0; q < 16; q++) {
            float4 h4 = hrow[q], w4 = wreg[q];
            acc += w4.x * h4.x + w4.y * h4.y + w4.z * h4.z + w4.w * h4.w;
        }
        acc += __shfl_xor_sync(0xffffffffu, acc, 4);
        acc += __shfl_xor_sync(0xffffffffu, acc, 2);
        acc += __shfl_xor_sync(0xffffffffu, acc, 1);
        if (cg == 0) gsum[lr] = acc;
        __syncthreads();

        if (owner) {
            int j = tid >> 3;
            float vi = sigf(gi + gsum[0 + j]);
            float vf = sigf(gf + gsum[8 + j]);
            float vg = tanhf(gg + gsum[16 + j]);
            float vo = sigf(go + gsum[24 + j]);
            cstate = vf * cstate + vi * vg;
            float h = vo * tanhf(cstate);
            hp[(size_t)t * HIDN + jglob] = h;
            __threadfence();   // make h visible gpu-wide before the counter bump
        }
        __syncthreads();
        if (tid == 0) atomicAdd(&rdy[t], 1);
    }
}

// ---------------- feats = [h_f ; h_b] @ h2t_w^T + h2t_b ---------------------
__global__ void feats_kernel(const float* __restrict__ h2t_w,
                             const float* __restrict__ h2t_b) {
    int t = blockIdx.x;
    int tid = threadIdx.x;
    int w = tid >> 5, lane = tid & 31;   // 11 warps, one per tag
    const float* hf = g_h[0] + (size_t)t * HIDN;
    const float* hb = g_h[1] + (size_t)t * HIDN;
    const float* wr = h2t_w + w * (2 * HIDN);
    float acc = 0.0f;
    #pragma unroll
    for (int it = 0; it < 16; it++) {
        int k = lane + it * 32;
        acc += wr[k] * hf[k];
        acc += wr[512 + k] * hb[k];
    }
    #pragma unroll
    for (int o = 16; o > 0; o >>= 1) acc += __shfl_down_sync(0xffffffffu, acc, o);
    if (lane == 0) g_feats[t * 16 + w] = acc + h2t_b[w];
}

// ---------------- Viterbi + backtrack (single block, bptrs in SMEM) ---------
__global__ void viterbi_kernel(const float* __restrict__ trans,
                               float* __restrict__ out, int out_size) {
    __shared__ unsigned char bp[SEQ][NTAG];   // 45 KB
    __shared__ float fv[16];
    int tid = threadIdx.x;

    float trow[NTAG];
    if (tid < NTAG) {
        #pragma unroll
        for (int j = 0; j < NTAG; j++) trow[j] = trans[tid * NTAG + j];
        fv[tid] = (tid == STARTT) ? 0.0f : NEGV;
    }
    __syncwarp();

    for (int t = 0; t < SEQ; t++) {
        float featv = (tid < NTAG) ? g_feats[t * 16 + tid] : 0.0f;
        float best = -3.4e38f; int arg = 0;
        if (tid < NTAG) {
            #pragma unroll
            for (int j = 0; j < NTAG; j++) {
                float v = fv[j] + trow[j];
                if (v > best) { best = v; arg = j; }
            }
        }
        __syncwarp();
        if (tid < NTAG) {
            fv[tid] = best + featv;
            bp[t][tid] = (unsigned char)arg;
        }
        __syncwarp();
    }

    if (tid == 0) {
        float bestv = -3.4e38f; int bi = 0;
        #pragma unroll
        for (int i = 0; i < NTAG; i++) {
            float v = fv[i] + trans[STOPT * NTAG + i];
            if (i == STARTT || i == STOPT) v = NEGV;
            if (v > bestv) { bestv = v; bi = i; }
        }
        if (out_size > 0) out[0] = bestv;
        int tag = bi;
        for (int t = SEQ - 1; t >= 0; t--) {
            if (1 + t < out_size) out[1 + t] = (float)tag;
            tag = bp[t][tag];
        }
    }
}

// ---------------- launch --------------------------------------------------
extern "C" void kernel_launch(void* const* d_in, const int* in_sizes, int n_in,
                              void* d_out, int out_size) {
    const int*   sentence = (const int*)d_in[0];
    const int*   chars    = (const int*)d_in[1];
    // d_in[2] = chars2_length (unused by reference), d_in[3] = d (unused)
    const float* word_emb = (const float*)d_in[4];
    const float* char_emb = (const float*)d_in[5];
    const float* conv_w   = (const float*)d_in[6];
    const float* conv_b   = (const float*)d_in[7];
    const float* Wih_f    = (const float*)d_in[8];
    const float* Whh_f    = (const float*)d_in[9];
    const float* bih_f    = (const float*)d_in[10];
    const float* bhh_f    = (const float*)d_in[11];
    const float* Wih_b    = (const float*)d_in[12];
    const float* Whh_b    = (const float*)d_in[13];
    const float* bih_b    = (const float*)d_in[14];
    const float* bhh_b    = (const float*)d_in[15];
    const float* h2t_w    = (const float*)d_in[16];
    const float* h2t_b    = (const float*)d_in[17];
    const float* trans    = (const float*)d_in[18];
    float* out = (float*)d_out;

    zero_ready_kernel<<<32, 256>>>();
    embed_kernel<<<SEQ, 128>>>(sentence, chars, word_emb, char_emb, conv_w, conv_b);
    dim3 gg(NGATE / 64, SEQ / 64, 2);
    gemm_kernel<<<gg, 256>>>(Wih_f, Wih_b, bih_f, bhh_f, bih_b, bhh_b);
    lstm_kernel<<<128, 256>>>(Whh_f, Whh_b);
    feats_kernel<<<SEQ, 352>>>(h2t_w, h2t_b);
    viterbi_kernel<<<1, 32>>>(trans, out, out_size);
}

// round 2
// speedup vs baseline: 1.4361x; 1.4361x over previous
#include <cuda_runtime.h>
#include <math.h>

#define SEQ   4096
#define LW    24
#define EMBD  300
#define CHOUT 25
#define CHE   25
#define HIDN  512
#define INPD  325      // EMB + CH_OUT
#define EMBS  328      // padded stride for 16B alignment
#define NTAG  11
#define STARTT 9
#define STOPT  10
#define NEGV  -10000.0f
#define NGATE 2048     // 4*HIDN
#define SENT  0x7FC00ABCu   // NaN payload sentinel: h in (-1,1) can never be NaN

// ---------------- static device scratch (no allocs allowed) ----------------
__device__ float g_emb[SEQ * EMBS];           // 5.4 MB  [t][k]
__device__ float g_G[2][SEQ * NGATE];         // 64 MB   Wih@x + bih + bhh
__device__ float g_h[2][SEQ * HIDN];          // 16 MB   hidden states (sentinel-poisoned)
__device__ float g_feats[SEQ * 16];           // padded [t][tag]

// ---------------- helpers ----------------
__device__ __forceinline__ float4 ld_rlx4(const float4* p) {
    float4 v;
    asm volatile("ld.relaxed.gpu.global.v4.f32 {%0,%1,%2,%3}, [%4];"
                 : "=f"(v.x), "=f"(v.y), "=f"(v.z), "=f"(v.w) : "l"(p));
    return v;
}
__device__ __forceinline__ void st_rlx(float* p, float v) {
    asm volatile("st.relaxed.gpu.global.f32 [%0], %1;" :: "l"(p), "f"(v));
}
__device__ __forceinline__ float sigf(float x) {
    return __fdividef(1.0f, 1.0f + __expf(-x));
}
__device__ __forceinline__ float tanh_fast(float x) {
    // tanh(x) = 2*sigmoid(2x) - 1 ; saturates correctly for large |x|
    return __fdividef(2.0f, 1.0f + __expf(-2.0f * x)) - 1.0f;
}

// ---------------- poison hidden-state buffer (data-as-flag protocol) --------
__global__ void poison_kernel() {
    int i = blockIdx.x * blockDim.x + threadIdx.x;   // 1M float4 = 16 MB
    float s = __uint_as_float(SENT);
    ((float4*)&g_h[0][0])[i] = make_float4(s, s, s, s);
}

// ---------------- char CNN + word-embedding gather --------------------------
__global__ void embed_kernel(const int* __restrict__ sentence,
                             const int* __restrict__ chars,
                             const float* __restrict__ word_emb,
                             const float* __restrict__ char_emb,
                             const float* __restrict__ conv_w,
                             const float* __restrict__ conv_b) {
    int s = blockIdx.x;
    int tid = threadIdx.x;
    __shared__ float ce[LW][CHE];
    __shared__ float co[CHOUT][26];
    __shared__ int   cidx[LW];

    if (tid < LW) cidx[tid] = chars[s * LW + tid];
    __syncthreads();
    for (int idx = tid; idx < LW * CHE; idx += blockDim.x) {
        int r = idx / CHE, e = idx % CHE;
        ce[r][e] = char_emb[cidx[r] * CHE + e];
    }
    __syncthreads();
    for (int idx = tid; idx < CHOUT * 26; idx += blockDim.x) {
        int o = idx / 26, p = idx % 26;
        float sum = 0.0f;
        #pragma unroll
        for (int kh = 0; kh < 3; kh++) {
            int r = p - 2 + kh;
            if (r >= 0 && r < LW) {
                const float* w = conv_w + (o * 3 + kh) * CHE;
                float ss = 0.0f;
                #pragma unroll
                for (int e = 0; e < CHE; e++) ss += ce[r][e] * w[e];
                sum += ss;
            }
        }
        co[o][p] = sum;
    }
    __syncthreads();
    if (tid < CHOUT) {
        float m = -3.4e38f;
        #pragma unroll
        for (int p = 0; p < 26; p++) m = fmaxf(m, co[tid][p]);
        g_emb[s * EMBS + EMBD + tid] = m + conv_b[tid];
    }
    int wi = sentence[s];
    const float4* src = (const float4*)(word_emb + (size_t)wi * EMBD);
    float4* dst = (float4*)(g_emb + (size_t)s * EMBS);
    for (int i = tid; i < EMBD / 4; i += blockDim.x) dst[i] = src[i];
}

// ---------------- G = emb @ Wih^T + (bih + bhh) -----------------------------
__global__ __launch_bounds__(256) void gemm_kernel(
    const float* __restrict__ Wihf, const float* __restrict__ Wihb,
    const float* __restrict__ bihf, const float* __restrict__ bhhf,
    const float* __restrict__ bihb, const float* __restrict__ bhhb) {
    int dir = blockIdx.z;
    const float* Wih = dir ? Wihb : Wihf;
    const float* bih = dir ? bihb : bihf;
    const float* bhh = dir ? bhhb : bhhf;
    int bm = blockIdx.y * 64;
    int bn = blockIdx.x * 64;
    int tid = threadIdx.x;
    int tx = tid & 15, ty = tid >> 4;

    __shared__ __align__(16) float As[8][68];
    __shared__ __align__(16) float Bs[8][68];

    float acc[4][4] = {};
    for (int k0 = 0; k0 < INPD; k0 += 8) {
        #pragma unroll
        for (int q = 0; q < 2; q++) {
            int idx = tid + q * 256;
            int kk = idx & 7, m = idx >> 3;
            int k = k0 + kk;
            As[kk][m] = (k < INPD) ? g_emb[(size_t)(bm + m) * EMBS + k] : 0.0f;
            Bs[kk][m] = (k < INPD) ? Wih[(size_t)(bn + m) * INPD + k] : 0.0f;
        }
        __syncthreads();
        #pragma unroll
        for (int kk = 0; kk < 8; kk++) {
            float4 a = *(const float4*)&As[kk][ty * 4];
            float4 b = *(const float4*)&Bs[kk][tx * 4];
            float av[4] = {a.x, a.y, a.z, a.w};
            float bv[4] = {b.x, b.y, b.z, b.w};
            #pragma unroll
            for (int i = 0; i < 4; i++)
                #pragma unroll
                for (int j = 0; j < 4; j++) acc[i][j] += av[i] * bv[j];
        }
        __syncthreads();
    }
    float* Gp = g_G[dir];
    #pragma unroll
    for (int i = 0; i < 4; i++) {
        int t = bm + ty * 4 + i;
        #pragma unroll
        for (int j = 0; j < 4; j++) {
            int n = bn + tx * 4 + j;
            Gp[(size_t)t * NGATE + n] = acc[i][j] + bih[n] + bhh[n];
        }
    }
}

// ---------------- persistent BiLSTM recurrence -------------------------------
// 128 blocks (64/dir), 256 threads. Sync protocol: data-as-flag. Consumers
// spin on the h vector itself (L1-bypassing relaxed loads) until every lane
// differs from the NaN sentinel. No atomics, no membar, one L2 round trip.
__global__ __launch_bounds__(256, 1) void lstm_kernel(
    const float* __restrict__ Whhf, const float* __restrict__ Whhb) {
    int dir = blockIdx.x >> 6;
    int b = blockIdx.x & 63;
    int tid = threadIdx.x;
    int lr = tid >> 3;     // local gate row 0..31
    int cg = tid & 7;      // column group (64 cols each)
    int gate = lr >> 3, jj = lr & 7;
    int grow = gate * HIDN + b * 8 + jj;
    const float* Whh = dir ? Whhb : Whhf;

    // 64 weights per thread in registers for the whole sequence
    float4 wreg[16];
    const float4* wsrc = (const float4*)(Whh + (size_t)grow * HIDN + cg * 64);
    #pragma unroll
    for (int q = 0; q < 16; q++) wreg[q] = wsrc[q];

    __shared__ float4 hs4[8 * 17];   // swizzled h_prev
    __shared__ float  gsum[32];

    const float* Gp = g_G[dir];
    float* hp = g_h[dir];
    float cstate = 0.0f;
    float gn0 = 0.f, gn1 = 0.f, gn2 = 0.f, gn3 = 0.f;

    // prefetch G for step 0
    if (tid < 8) {
        int t0 = dir ? (SEQ - 1) : 0;
        const float* gr = Gp + (size_t)t0 * NGATE + b * 8 + tid;
        gn0 = gr[0]; gn1 = gr[512]; gn2 = gr[1024]; gn3 = gr[1536];
    }

    for (int s = 0; s < SEQ; s++) {
        int t = dir ? (SEQ - 1 - s) : s;
        float gi = gn0, gf = gn1, gg = gn2, go = gn3;
        // prefetch G for next step (hides 577-cyc DRAM latency)
        if (tid < 8 && s + 1 < SEQ) {
            int tn = dir ? (t - 1) : (t + 1);
            const float* gr = Gp + (size_t)tn * NGATE + b * 8 + tid;
            gn0 = gr[0]; gn1 = gr[512]; gn2 = gr[1024]; gn3 = gr[1536];
        }

        if (s > 0) {
            int pt = dir ? (t + 1) : (t - 1);
            if (tid < 128) {
                const float4* src = (const float4*)(hp + (size_t)pt * HIDN) + tid;
                float4 v;
                do {
                    v = ld_rlx4(src);
                } while (__float_as_uint(v.x) == SENT || __float_as_uint(v.y) == SENT ||
                         __float_as_uint(v.z) == SENT || __float_as_uint(v.w) == SENT);
                hs4[(tid >> 4) * 17 + (tid & 15)] = v;
            }
        } else {
            if (tid < 136) hs4[tid] = make_float4(0.f, 0.f, 0.f, 0.f);
        }
        __syncthreads();

        // partial dot: 64 columns per thread, 4 independent accumulators
        float a0 = 0.f, a1 = 0.f, a2 = 0.f, a3 = 0.f;
        const float4* hrow = hs4 + cg * 17;
        #pragma unroll
        for (int q = 0; q < 16; q++) {
            float4 h4 = hrow[q], w4 = wreg[q];
            a0 = fmaf(w4.x, h4.x, a0);
            a1 = fmaf(w4.y, h4.y, a1);
            a2 = fmaf(w4.z, h4.z, a2);
            a3 = fmaf(w4.w, h4.w, a3);
        }
        float acc = (a0 + a1) + (a2 + a3);
        acc += __shfl_xor_sync(0xffffffffu, acc, 4);
        acc += __shfl_xor_sync(0xffffffffu, acc, 2);
        acc += __shfl_xor_sync(0xffffffffu, acc, 1);
        if (cg == 0) gsum[lr] = acc;
        __syncthreads();

        // gates: single warp, lanes 0..7
        if (tid < 8) {
            float vi = sigf(gi + gsum[tid]);
            float vf = sigf(gf + gsum[8 + tid]);
            float vg = tanh_fast(gg + gsum[16 + tid]);
            float vo = sigf(go + gsum[24 + tid]);
            cstate = vf * cstate + vi * vg;
            float h = vo * tanh_fast(cstate);
            // 8 lanes, contiguous 32B: coalesces into one sector store
            st_rlx(hp + (size_t)t * HIDN + b * 8 + tid, h);
        }
        // no trailing barrier needed: hs4/gsum reuse is fenced by the two
        // barriers inside the next iteration
    }
}

// ---------------- feats = [h_f ; h_b] @ h2t_w^T + h2t_b ---------------------
__global__ void feats_kernel(const float* __restrict__ h2t_w,
                             const float* __restrict__ h2t_b) {
    int t = blockIdx.x;
    int tid = threadIdx.x;
    int w = tid >> 5, lane = tid & 31;
    const float* hf = g_h[0] + (size_t)t * HIDN;
    const float* hb = g_h[1] + (size_t)t * HIDN;
    const float* wr = h2t_w + w * (2 * HIDN);
    float acc = 0.0f;
    #pragma unroll
    for (int it = 0; it < 16; it++) {
        int k = lane + it * 32;
        acc += wr[k] * hf[k];
        acc += wr[512 + k] * hb[k];
    }
    #pragma unroll
    for (int o = 16; o > 0; o >>= 1) acc += __shfl_down_sync(0xffffffffu, acc, o);
    if (lane == 0) g_feats[t * 16 + w] = acc + h2t_b[w];
}

// ---------------- Viterbi + backtrack (single block, bptrs in SMEM) ---------
__global__ void viterbi_kernel(const float* __restrict__ trans,
                               float* __restrict__ out, int out_size) {
    __shared__ unsigned char bp[SEQ][NTAG];   // 45 KB
    __shared__ float fv[16];
    int tid = threadIdx.x;

    float trow[NTAG];
    if (tid < NTAG) {
        #pragma unroll
        for (int j = 0; j < NTAG; j++) trow[j] = trans[tid * NTAG + j];
        fv[tid] = (tid == STARTT) ? 0.0f : NEGV;
    }
    __syncwarp();

    for (int t = 0; t < SEQ; t++) {
        float featv = (tid < NTAG) ? g_feats[t * 16 + tid] : 0.0f;
        float best = -3.4e38f; int arg = 0;
        if (tid < NTAG) {
            #pragma unroll
            for (int j = 0; j < NTAG; j++) {
                float v = fv[j] + trow[j];
                if (v > best) { best = v; arg = j; }
            }
        }
        __syncwarp();
        if (tid < NTAG) {
            fv[tid] = best + featv;
            bp[t][tid] = (unsigned char)arg;
        }
        __syncwarp();
    }

    if (tid == 0) {
        float bestv = -3.4e38f; int bi = 0;
        #pragma unroll
        for (int i = 0; i < NTAG; i++) {
            float v = fv[i] + trans[STOPT * NTAG + i];
            if (i == STARTT || i == STOPT) v = NEGV;
            if (v > bestv) { bestv = v; bi = i; }
        }
        if (out_size > 0) out[0] = bestv;
        int tag = bi;
        for (int t = SEQ - 1; t >= 0; t--) {
            if (1 + t < out_size) out[1 + t] = (float)tag;
            tag = bp[t][tag];
        }
    }
}

// ---------------- launch --------------------------------------------------
extern "C" void kernel_launch(void* const* d_in, const int* in_sizes, int n_in,
                              void* d_out, int out_size) {
    const int*   sentence = (const int*)d_in[0];
    const int*   chars    = (const int*)d_in[1];
    const float* word_emb = (const float*)d_in[4];
    const float* char_emb = (const float*)d_in[5];
    const float* conv_w   = (const float*)d_in[6];
    const float* conv_b   = (const float*)d_in[7];
    const float* Wih_f    = (const float*)d_in[8];
    const float* Whh_f    = (const float*)d_in[9];
    const float* bih_f    = (const float*)d_in[10];
    const float* bhh_f    = (const float*)d_in[11];
    const float* Wih_b    = (const float*)d_in[12];
    const float* Whh_b    = (const float*)d_in[13];
    const float* bih_b    = (const float*)d_in[14];
    const float* bhh_b    = (const float*)d_in[15];
    const float* h2t_w    = (const float*)d_in[16];
    const float* h2t_b    = (const float*)d_in[17];
    const float* trans    = (const float*)d_in[18];
    float* out = (float*)d_out;

    poison_kernel<<<4096, 256>>>();   // 16 MB of g_h -> sentinel
    embed_kernel<<<SEQ, 128>>>(sentence, chars, word_emb, char_emb, conv_w, conv_b);
    dim3 gg(NGATE / 64, SEQ / 64, 2);
    gemm_kernel<<<gg, 256>>>(Wih_f, Wih_b, bih_f, bhh_f, bih_b, bhh_b);
    lstm_kernel<<<128, 256>>>(Whh_f, Whh_b);
    feats_kernel<<<SEQ, 352>>>(h2t_w, h2t_b);
    viterbi_kernel<<<1, 32>>>(trans, out, out_size);
}